// round 16
// baseline (speedup 1.0000x reference)
#include <cuda_runtime.h>
#include <cuda_fp16.h>

#define HH 512
#define WW 512
#define CC 128
#define NPTS 524288
#define PLANE_ELEMS (CC * HH * WW)

#define T64_BLOCKS (2 * HH * (WW / 64))   // 8192: 64-wide half-channel tiles
#define SETUP_BLOCKS (NPTS / 256)          // 2048
#define K1_BLOCKS (T64_BLOCKS + SETUP_BLOCKS)  // 10240 = 2048 * 5 (4:1 mix)
#define PASS_BLOCKS (NPTS / 32)            // 16384: 32 points/block, 8 lanes/pt
#define K2_BLOCKS (PASS_BLOCKS + T64_BLOCKS)  // 24576, 2:1 interleave

// Transposed fp16 planes [H][W][C] (channel-last).
__device__ __align__(16) __half g_uvT[PLANE_ELEMS];
__device__ __align__(16) __half g_stT[PLANE_ELEMS];
// 16B per-point record: {uvBase, stBase, h2(wxu,wyu), h2(wxs,wys)}
__device__ __align__(16) uint4 g_rec[NPTS];
// fp16 partials from pass A: 8 halfs per point (one uint4).
__device__ __align__(16) uint4 g_part[NPTS];

__device__ __forceinline__ unsigned packw2(float a, float b) {
    __half2 h = __floats2half2_rn(a, b);
    return *(unsigned*)&h;
}
__device__ __forceinline__ __half2 u2h(unsigned u) { return *(__half2*)&u; }

// ---------------------------------------------------------------------------
// 64-wide half-channel transpose tile: [C,H,W] f32 -> [H,W,C] f16, 64 ch.
// STREAM=true uses evict-first hints (fused with a pass that owns L2).
// ---------------------------------------------------------------------------
template <int CHOFF, bool STREAM>
__device__ __forceinline__ void transpose64(
    int tbid, int tid, const float* __restrict__ uv,
    const float* __restrict__ st) {
    __shared__ float tile[64][65];
    const int plane = tbid >> 12;            // /4096
    const int rem = tbid & 4095;
    const int y = rem >> 3;
    const int x0 = (rem & 7) * 64;
    const int tx = tid & 31;
    const int wa = tid >> 5;  // 0..7

    const float* src = plane ? st : uv;
    __half* dst = plane ? g_stT : g_uvT;

    #pragma unroll
    for (int i = 0; i < 8; i++) {
        const int c = wa + i * 8;  // 0..63
        const float* sp = &src[(size_t)(CHOFF + c) * (HH * WW) + y * WW + x0 + tx];
        if (STREAM) {
            tile[c][tx] = __ldcs(sp);
            tile[c][tx + 32] = __ldcs(sp + 32);
        } else {
            tile[c][tx] = *sp;
            tile[c][tx + 32] = sp[32];
        }
    }
    __syncthreads();

    // Write: warp = fixed xi, lanes sweep channels -> one 128B line per store.
    const int c2 = tx * 2;  // 0..62
    #pragma unroll
    for (int i = 0; i < 8; i++) {
        const int xi = wa + i * 8;  // 0..63
        __half2 v = __floats2half2_rn(tile[c2][xi], tile[c2 + 1][xi]);
        __half2* dp = (__half2*)(dst + (size_t)(y * WW + x0 + xi) * CC + CHOFF + c2);
        if (STREAM) __stcs((uint*)dp, *(uint*)&v);
        else *dp = v;
    }
}

// ---------------------------------------------------------------------------
// Per-point setup: compute record from coords.
// ---------------------------------------------------------------------------
__device__ __forceinline__ void setup_body(
    int sbid, int tid, const float4* __restrict__ xs,
    const float* __restrict__ b) {
    const int i = sbid * 256 + tid;
    const float4 p = __ldcs(&xs[i]);

    const float ixu = __fdividef(p.x - b[0], b[4] - b[0]) * (WW - 1);
    const float iyu = __fdividef(p.y - b[1], b[5] - b[1]) * (HH - 1);
    const float ixs = __fdividef(p.z - b[2], b[6] - b[2]) * (WW - 1);
    const float iys = __fdividef(p.w - b[3], b[7] - b[3]) * (HH - 1);

    const int xu0 = min(max(__float2int_rd(ixu), 0), WW - 2);
    const int yu0 = min(max(__float2int_rd(iyu), 0), HH - 2);
    const int xs0 = min(max(__float2int_rd(ixs), 0), WW - 2);
    const int ys0 = min(max(__float2int_rd(iys), 0), HH - 2);

    uint4 r;
    r.x = (unsigned)((yu0 * WW + xu0) * CC);
    r.y = (unsigned)((ys0 * WW + xs0) * CC);
    r.z = packw2(ixu - (float)xu0, iyu - (float)yu0);
    r.w = packw2(ixs - (float)xs0, iys - (float)ys0);
    g_rec[i] = r;
}

// ---------------------------------------------------------------------------
// Per-point bilinear pass body: 8 lanes/point, lane gl = channels CHOFF+8*gl.
// ---------------------------------------------------------------------------
template <int CHOFF, bool FIRST>
__device__ __forceinline__ void pass_body(int pbid, int tid,
                                          float* __restrict__ out) {
    const int p = pbid * 32 + (tid >> 3);
    const int gl = tid & 7;

    // Default caching: rec is re-read by k3, keep it L2-resident.
    const uint4 r = g_rec[p];

    const __half* U = g_uvT + r.x + CHOFF + gl * 8;
    const __half* S = g_stT + r.y + CHOFF + gl * 8;

    const uint4 u00 = *(const uint4*)(U);
    const uint4 u01 = *(const uint4*)(U + CC);
    const uint4 u10 = *(const uint4*)(U + WW * CC);
    const uint4 u11 = *(const uint4*)(U + WW * CC + CC);
    const uint4 s00 = *(const uint4*)(S);
    const uint4 s01 = *(const uint4*)(S + CC);
    const uint4 s10 = *(const uint4*)(S + WW * CC);
    const uint4 s11 = *(const uint4*)(S + WW * CC + CC);

    const __half2 one = __float2half2_rn(1.f);

    __half2 au[4], av[4];
    {
        const __half2 h = u2h(r.z);  // (wxu, wyu)
        const __half2 wx = __low2half2(h), wy = __high2half2(h);
        const __half2 ix = __hsub2(one, wx), iy = __hsub2(one, wy);
        const __half2 w00 = __hmul2(ix, iy), w01 = __hmul2(wx, iy);
        const __half2 w10 = __hmul2(ix, wy), w11 = __hmul2(wx, wy);
        const __half2* p00 = (const __half2*)&u00;
        const __half2* p01 = (const __half2*)&u01;
        const __half2* p10 = (const __half2*)&u10;
        const __half2* p11 = (const __half2*)&u11;
        #pragma unroll
        for (int j = 0; j < 4; j++) {
            __half2 a = __hmul2(p00[j], w00);
            a = __hfma2(p01[j], w01, a);
            a = __hfma2(p10[j], w10, a);
            au[j] = __hfma2(p11[j], w11, a);
        }
    }
    {
        const __half2 h = u2h(r.w);  // (wxs, wys)
        const __half2 wx = __low2half2(h), wy = __high2half2(h);
        const __half2 ix = __hsub2(one, wx), iy = __hsub2(one, wy);
        const __half2 w00 = __hmul2(ix, iy), w01 = __hmul2(wx, iy);
        const __half2 w10 = __hmul2(ix, wy), w11 = __hmul2(wx, wy);
        const __half2* p00 = (const __half2*)&s00;
        const __half2* p01 = (const __half2*)&s01;
        const __half2* p10 = (const __half2*)&s10;
        const __half2* p11 = (const __half2*)&s11;
        #pragma unroll
        for (int j = 0; j < 4; j++) {
            __half2 a = __hmul2(p00[j], w00);
            a = __hfma2(p01[j], w01, a);
            a = __hfma2(p10[j], w10, a);
            av[j] = __hfma2(p11[j], w11, a);
        }
    }

    float f[8];
    #pragma unroll
    for (int j = 0; j < 4; j++) {
        const float2 t = __half22float2(__hmul2(au[j], av[j]));
        f[2 * j] = t.x;
        f[2 * j + 1] = t.y;
    }

    #pragma unroll
    for (int s = 4; s >= 1; s >>= 1) {
        #pragma unroll
        for (int j = 0; j < 8; j++)
            f[j] += __shfl_xor_sync(0xffffffffu, f[j], s);
    }

    if (gl == 0) {
        if (FIRST) {
            uint4 pk;
            pk.x = packw2(f[0], f[1]);
            pk.y = packw2(f[2], f[3]);
            pk.z = packw2(f[4], f[5]);
            pk.w = packw2(f[6], f[7]);
            __stcs(&g_part[p], pk);
        } else {
            const uint4 pk = __ldcs(&g_part[p]);
            const float2 a0 = __half22float2(u2h(pk.x));
            const float2 a1 = __half22float2(u2h(pk.y));
            const float2 a2 = __half22float2(u2h(pk.z));
            const float2 a3 = __half22float2(u2h(pk.w));
            float4 o0, o1;
            o0.x = 1.f / (1.f + __expf(-(f[0] + a0.x)));
            o0.y = 1.f / (1.f + __expf(-(f[1] + a0.y)));
            o0.z = 1.f / (1.f + __expf(-(f[2] + a1.x)));
            o0.w = 1.f / (1.f + __expf(-(f[3] + a1.y)));
            o1.x = 1.f / (1.f + __expf(-(f[4] + a2.x)));
            o1.y = 1.f / (1.f + __expf(-(f[5] + a2.y)));
            o1.z = 1.f / (1.f + __expf(-(f[6] + a3.x)));
            o1.w = 1.f / (1.f + __expf(-(f[7] + a3.y)));
            __stcs(&((float4*)out)[p * 2], o0);
            __stcs(&((float4*)out)[p * 2 + 1], o1);
        }
    }
}

// ---------------------------------------------------------------------------
// K1: transpose ch 0-63 interleaved 4:1 with per-point setup blocks so the
// latency-bound setup work rides inside the DRAM stream (no idle tail).
// ---------------------------------------------------------------------------
__global__ __launch_bounds__(256) void k1_kernel(
    const float* __restrict__ uv, const float* __restrict__ st,
    const float4* __restrict__ xs, const float* __restrict__ b) {
    const int bid = blockIdx.x;
    const int tid = threadIdx.x;
    const int g = bid / 5;
    const int rr = bid - g * 5;
    if (rr == 4) {
        setup_body(g, tid, xs, b);
    } else {
        transpose64<0, false>(g * 4 + rr, tid, uv, st);
    }
}

// ---------------------------------------------------------------------------
// K2 (fused): passA (ch 0-63, LTS-bound) || transpose ch 64-127 (DRAM-bound).
// 2:1 interleave.
// ---------------------------------------------------------------------------
__global__ __launch_bounds__(256) void k2_kernel(
    const float* __restrict__ uv, const float* __restrict__ st,
    float* __restrict__ out) {
    const int bid = blockIdx.x;
    const int tid = threadIdx.x;
    const int g = bid / 3;
    const int rr = bid - g * 3;
    if (rr == 2) {
        transpose64<64, true>(g, tid, uv, st);
    } else {
        pass_body<0, true>(g * 2 + rr, tid, out);
    }
}

// ---------------------------------------------------------------------------
// K3: passB (ch 64-127) + combine + sigmoid + store.
// ---------------------------------------------------------------------------
__global__ __launch_bounds__(256) void k3_kernel(float* __restrict__ out) {
    pass_body<64, false>(blockIdx.x, threadIdx.x, out);
}

// ---------------------------------------------------------------------------
extern "C" void kernel_launch(void* const* d_in, const int* in_sizes, int n_in,
                              void* d_out, int out_size) {
    const float* x = (const float*)d_in[0];
    const float* uv = (const float*)d_in[1];
    const float* st = (const float*)d_in[2];
    const float* bounds = (const float*)d_in[3];
    float* out = (float*)d_out;

    k1_kernel<<<K1_BLOCKS, 256>>>(uv, st, (const float4*)x, bounds);
    k2_kernel<<<K2_BLOCKS, 256>>>(uv, st, out);
    k3_kernel<<<PASS_BLOCKS, 256>>>(out);
}